// round 1
// baseline (speedup 1.0000x reference)
#include <cuda_runtime.h>
#include <cstdint>
#include <cstddef>

#define SEQ   4096
#define BATCH 8
#define DM    512
#define NHEAD 8
#define DK    64
#define PHI   128
#define ROWS  (SEQ * BATCH)   // 32768 tokens

// ---------------------------------------------------------------------------
// Static device scratch (no allocations allowed). Padded by one extra time
// step (BATCH tokens) so the scan kernel can prefetch one step ahead without
// branches or OOB.
// ---------------------------------------------------------------------------
__device__ float g_qraw[(size_t)ROWS * DM];
__device__ float g_kraw[(size_t)ROWS * DM];
__device__ float g_v   [(size_t)(ROWS + BATCH) * DM];
__device__ float g_qphi[(size_t)(ROWS + BATCH) * NHEAD * PHI];
__device__ float g_kphi[(size_t)(ROWS + BATCH) * NHEAD * PHI];
__device__ float g_beta[(size_t)(ROWS + BATCH) * NHEAD];
__device__ float g_att [(size_t)ROWS * DM];

// ---------------------------------------------------------------------------
// tf32 helpers
// ---------------------------------------------------------------------------
__device__ __forceinline__ uint32_t f2tf32(float x) {
    uint32_t r;
    asm("cvt.rna.tf32.f32 %0, %1;" : "=r"(r) : "f"(x));
    return r;
}

__device__ __forceinline__ void mma_tf32(float c[4], const uint32_t a[4], const uint32_t b[2]) {
    asm volatile(
        "mma.sync.aligned.m16n8k8.row.col.f32.tf32.tf32.f32 "
        "{%0,%1,%2,%3}, {%4,%5,%6,%7}, {%8,%9}, {%0,%1,%2,%3};\n"
        : "+f"(c[0]), "+f"(c[1]), "+f"(c[2]), "+f"(c[3])
        : "r"(a[0]), "r"(a[1]), "r"(a[2]), "r"(a[3]), "r"(b[0]), "r"(b[1]));
}

// ---------------------------------------------------------------------------
// GEMM: C[M,N] = A[M,K] * B[K,N] (+ bias), all row-major fp32, tf32 tensor
// cores. Requires M%128==0, N%128==0, K%16==0 (true for all uses here).
// Block tile 128x128x16, 256 threads, warp tile 64x32 (2x4 warps).
// ---------------------------------------------------------------------------
#define BM 128
#define BN 128
#define BK 16
#define ASTRIDE 20    // padded: conflict-free A frag LDS
#define BSTRIDE 136   // padded: conflict-free B frag LDS

__global__ void __launch_bounds__(256, 2)
gemm_tf32(const float* __restrict__ A, const float* __restrict__ B,
          const float* __restrict__ bias, float* __restrict__ C,
          int M, int N, int K)
{
    __shared__ uint32_t As[BM * ASTRIDE];
    __shared__ uint32_t Bs[BK * BSTRIDE];

    const int tid  = threadIdx.x;
    const int warp = tid >> 5;
    const int lane = tid & 31;
    const int wm   = warp >> 2;   // 0..1
    const int wn   = warp & 3;    // 0..3
    const int g    = lane >> 2;   // groupID 0..7
    const int t4   = lane & 3;    // thread-in-group 0..3
    const int rowBase = blockIdx.y * BM;
    const int colBase = blockIdx.x * BN;

    float acc[4][4][4];
    #pragma unroll
    for (int i = 0; i < 4; ++i)
        #pragma unroll
        for (int j = 0; j < 4; ++j)
            #pragma unroll
            for (int r = 0; r < 4; ++r) acc[i][j][r] = 0.f;

    for (int k0 = 0; k0 < K; k0 += BK) {
        #pragma unroll
        for (int i = 0; i < 2; ++i) {
            int f = tid + i * 256;
            // A tile: 128 rows x 16 cols = 512 float4
            int ar = f >> 2, ac = (f & 3) << 2;
            float4 av = *reinterpret_cast<const float4*>(
                A + (size_t)(rowBase + ar) * K + k0 + ac);
            As[ar * ASTRIDE + ac + 0] = f2tf32(av.x);
            As[ar * ASTRIDE + ac + 1] = f2tf32(av.y);
            As[ar * ASTRIDE + ac + 2] = f2tf32(av.z);
            As[ar * ASTRIDE + ac + 3] = f2tf32(av.w);
            // B tile: 16 rows x 128 cols = 512 float4
            int br = f >> 5, bc = (f & 31) << 2;
            float4 bv = *reinterpret_cast<const float4*>(
                B + (size_t)(k0 + br) * N + colBase + bc);
            Bs[br * BSTRIDE + bc + 0] = f2tf32(bv.x);
            Bs[br * BSTRIDE + bc + 1] = f2tf32(bv.y);
            Bs[br * BSTRIDE + bc + 2] = f2tf32(bv.z);
            Bs[br * BSTRIDE + bc + 3] = f2tf32(bv.w);
        }
        __syncthreads();

        #pragma unroll
        for (int kk = 0; kk < BK; kk += 8) {
            uint32_t afr[4][4];
            uint32_t bfr[4][2];
            #pragma unroll
            for (int mt = 0; mt < 4; ++mt) {
                int r0 = wm * 64 + mt * 16;
                afr[mt][0] = As[(r0 + g)     * ASTRIDE + kk + t4];
                afr[mt][1] = As[(r0 + 8 + g) * ASTRIDE + kk + t4];
                afr[mt][2] = As[(r0 + g)     * ASTRIDE + kk + 4 + t4];
                afr[mt][3] = As[(r0 + 8 + g) * ASTRIDE + kk + 4 + t4];
            }
            #pragma unroll
            for (int nt = 0; nt < 4; ++nt) {
                int c0 = wn * 32 + nt * 8;
                bfr[nt][0] = Bs[(kk + t4)     * BSTRIDE + c0 + g];
                bfr[nt][1] = Bs[(kk + 4 + t4) * BSTRIDE + c0 + g];
            }
            #pragma unroll
            for (int mt = 0; mt < 4; ++mt)
                #pragma unroll
                for (int nt = 0; nt < 4; ++nt)
                    mma_tf32(acc[mt][nt], afr[mt], bfr[nt]);
        }
        __syncthreads();
    }

    #pragma unroll
    for (int mt = 0; mt < 4; ++mt) {
        int r = rowBase + wm * 64 + mt * 16 + g;
        #pragma unroll
        for (int nt = 0; nt < 4; ++nt) {
            int c = colBase + wn * 32 + nt * 8 + 2 * t4;
            float b0 = 0.f, b1 = 0.f;
            if (bias) { b0 = bias[c]; b1 = bias[c + 1]; }
            C[(size_t)r * N + c]           = acc[mt][nt][0] + b0;
            C[(size_t)r * N + c + 1]       = acc[mt][nt][1] + b1;
            C[(size_t)(r + 8) * N + c]     = acc[mt][nt][2] + b0;
            C[(size_t)(r + 8) * N + c + 1] = acc[mt][nt][3] + b1;
        }
    }
}

// ---------------------------------------------------------------------------
// Gate: beta[t,h] = sigmoid(x[t,:] @ Wg[:,h]). One warp per token row.
// ---------------------------------------------------------------------------
__global__ void __launch_bounds__(256)
gate_kernel(const float* __restrict__ x, const float* __restrict__ Wg,
            float* __restrict__ beta)
{
    const int w    = (blockIdx.x * 256 + threadIdx.x) >> 5;  // token row
    const int lane = threadIdx.x & 31;
    const float* xr = x + (size_t)w * DM;

    float a0=0.f,a1=0.f,a2=0.f,a3=0.f,a4=0.f,a5=0.f,a6=0.f,a7=0.f;
    #pragma unroll
    for (int c = 0; c < 4; ++c) {
        int k = c * 128 + lane * 4;
        float4 xv = *reinterpret_cast<const float4*>(xr + k);
        float xs0 = xv.x, xs1 = xv.y, xs2 = xv.z, xs3 = xv.w;
        #pragma unroll
        for (int e = 0; e < 4; ++e) {
            float xe = (e == 0) ? xs0 : (e == 1) ? xs1 : (e == 2) ? xs2 : xs3;
            const float4* wr = reinterpret_cast<const float4*>(Wg + (size_t)(k + e) * NHEAD);
            float4 w0 = wr[0];
            float4 w1 = wr[1];
            a0 = fmaf(xe, w0.x, a0); a1 = fmaf(xe, w0.y, a1);
            a2 = fmaf(xe, w0.z, a2); a3 = fmaf(xe, w0.w, a3);
            a4 = fmaf(xe, w1.x, a4); a5 = fmaf(xe, w1.y, a5);
            a6 = fmaf(xe, w1.z, a6); a7 = fmaf(xe, w1.w, a7);
        }
    }
    #pragma unroll
    for (int off = 16; off > 0; off >>= 1) {
        a0 += __shfl_xor_sync(0xffffffffu, a0, off);
        a1 += __shfl_xor_sync(0xffffffffu, a1, off);
        a2 += __shfl_xor_sync(0xffffffffu, a2, off);
        a3 += __shfl_xor_sync(0xffffffffu, a3, off);
        a4 += __shfl_xor_sync(0xffffffffu, a4, off);
        a5 += __shfl_xor_sync(0xffffffffu, a5, off);
        a6 += __shfl_xor_sync(0xffffffffu, a6, off);
        a7 += __shfl_xor_sync(0xffffffffu, a7, off);
    }
    if (lane == 0) {
        float* bp = beta + (size_t)w * NHEAD;
        bp[0] = 1.f / (1.f + expf(-a0));
        bp[1] = 1.f / (1.f + expf(-a1));
        bp[2] = 1.f / (1.f + expf(-a2));
        bp[3] = 1.f / (1.f + expf(-a3));
        bp[4] = 1.f / (1.f + expf(-a4));
        bp[5] = 1.f / (1.f + expf(-a5));
        bp[6] = 1.f / (1.f + expf(-a6));
        bp[7] = 1.f / (1.f + expf(-a7));
    }
}

// ---------------------------------------------------------------------------
// DPFP: raw[t, h*64 .. h*64+63] -> phi[t, h, 0..127]
//   a = [relu(x), relu(-x)] (128);  y[j] = a[j]*a[(j-1) mod 128];
//   phi = y / (sum(y) + 1e-6)
// One warp per (token, head); lane owns a[4l..4l+3] (contiguous j).
// ---------------------------------------------------------------------------
__global__ void __launch_bounds__(256)
dpfp_kernel(const float* __restrict__ raw, float* __restrict__ phi)
{
    const int t    = blockIdx.x;
    const int h    = threadIdx.x >> 5;
    const int lane = threadIdx.x & 31;

    const float4 xv = *reinterpret_cast<const float4*>(
        raw + (size_t)t * DM + h * DK + ((lane & 15) << 2));
    const float sgn = (lane < 16) ? 1.f : -1.f;
    float a0 = fmaxf(sgn * xv.x, 0.f);
    float a1 = fmaxf(sgn * xv.y, 0.f);
    float a2 = fmaxf(sgn * xv.z, 0.f);
    float a3 = fmaxf(sgn * xv.w, 0.f);

    // neighbor a[4l-1] lives in lane l-1 (wraps: lane 0 <- lane 31 == a[127])
    float nbr = __shfl_sync(0xffffffffu, a3, (lane + 31) & 31);
    float y0 = a0 * nbr;
    float y1 = a1 * a0;
    float y2 = a2 * a1;
    float y3 = a3 * a2;

    float s = (y0 + y1) + (y2 + y3);
    #pragma unroll
    for (int off = 16; off > 0; off >>= 1)
        s += __shfl_xor_sync(0xffffffffu, s, off);
    float r = 1.f / (s + 1e-6f);

    float4 o = make_float4(y0 * r, y1 * r, y2 * r, y3 * r);
    *reinterpret_cast<float4*>(phi + ((size_t)t * NHEAD + h) * PHI + (lane << 2)) = o;
}

// ---------------------------------------------------------------------------
// Delta-rule scan. Rows of W are independent: one warp per (b,h,row),
// 4096 warps total. State = W[row, 0..127] (float4 per lane). Per step:
//   s   = <W_row, k>
//   d   = beta * (v[row] - s)
//   W  += d * k
//   out = <W_row, q>
// Next-step operands are prefetched (buffers are padded one step).
// ---------------------------------------------------------------------------
__global__ void __launch_bounds__(256)
scan_kernel(const float* __restrict__ qphi, const float* __restrict__ kphi,
            const float* __restrict__ v, const float* __restrict__ beta,
            float* __restrict__ att)
{
    const int w    = blockIdx.x * 8 + (threadIdx.x >> 5);  // 0..4095
    const int lane = threadIdx.x & 31;
    const int pair = w >> 6;          // b*NHEAD + h
    const int row  = w & 63;
    const int b    = pair >> 3;
    const int h    = pair & 7;

    const int KQ_STRIDE = BATCH * NHEAD * PHI;  // per time step (8192 floats)
    const int V_STRIDE  = BATCH * DM;           // 4096
    const int B_STRIDE  = BATCH * NHEAD;        // 64

    const float* kp = kphi + ((size_t)(b * NHEAD + h)) * PHI + (lane << 2);
    const float* qp = qphi + ((size_t)(b * NHEAD + h)) * PHI + (lane << 2);
    const float* vp = v    + (size_t)b * DM + h * DK + row;
    const float* bp = beta + (size_t)b * NHEAD + h;
    float*       op = att  + (size_t)b * DM + h * DK + row;

    float w0 = 0.f, w1 = 0.f, w2 = 0.f, w3 = 0.f;

    float4 kk = *reinterpret_cast<const float4*>(kp);
    float4 qq = *reinterpret_cast<const float4*>(qp);
    float  vv = *vp;
    float  be = *bp;

    for (int s = 0; s < SEQ; ++s) {
        kp += KQ_STRIDE; qp += KQ_STRIDE; vp += V_STRIDE; bp += B_STRIDE;
        const float4 kn = *reinterpret_cast<const float4*>(kp);
        const float4 qn = *reinterpret_cast<const float4*>(qp);
        const float  vn = *vp;
        const float  bn = *bp;

        float s1 = fmaf(w0, kk.x, fmaf(w1, kk.y, fmaf(w2, kk.z, w3 * kk.w)));
        #pragma unroll
        for (int off = 16; off > 0; off >>= 1)
            s1 += __shfl_xor_sync(0xffffffffu, s1, off);

        float d = be * (vv - s1);
        w0 = fmaf(d, kk.x, w0);
        w1 = fmaf(d, kk.y, w1);
        w2 = fmaf(d, kk.z, w2);
        w3 = fmaf(d, kk.w, w3);

        float o1 = fmaf(w0, qq.x, fmaf(w1, qq.y, fmaf(w2, qq.z, w3 * qq.w)));
        #pragma unroll
        for (int off = 16; off > 0; off >>= 1)
            o1 += __shfl_xor_sync(0xffffffffu, o1, off);

        if (lane == 0) *op = o1;
        op += V_STRIDE;

        kk = kn; qq = qn; vv = vn; be = bn;
    }
}

// ---------------------------------------------------------------------------
// Host launcher
// ---------------------------------------------------------------------------
extern "C" void kernel_launch(void* const* d_in, const int* in_sizes, int n_in,
                              void* d_out, int out_size)
{
    const float* x  = (const float*)d_in[0];
    const float* Wq = (const float*)d_in[1];
    const float* Wk = (const float*)d_in[2];
    const float* Wv = (const float*)d_in[3];
    const float* Wg = (const float*)d_in[4];
    const float* Wo = (const float*)d_in[5];
    const float* bo = (const float*)d_in[6];
    float* out = (float*)d_out;

    float *qraw, *kraw, *vbuf, *qphi, *kphi, *betab, *attb;
    cudaGetSymbolAddress((void**)&qraw,  g_qraw);
    cudaGetSymbolAddress((void**)&kraw,  g_kraw);
    cudaGetSymbolAddress((void**)&vbuf,  g_v);
    cudaGetSymbolAddress((void**)&qphi,  g_qphi);
    cudaGetSymbolAddress((void**)&kphi,  g_kphi);
    cudaGetSymbolAddress((void**)&betab, g_beta);
    cudaGetSymbolAddress((void**)&attb,  g_att);

    dim3 gg(DM / BN, ROWS / BM);  // (4, 256)

    gemm_tf32<<<gg, 256>>>(x, Wq, nullptr, qraw, ROWS, DM, DM);
    gemm_tf32<<<gg, 256>>>(x, Wk, nullptr, kraw, ROWS, DM, DM);
    gemm_tf32<<<gg, 256>>>(x, Wv, nullptr, vbuf, ROWS, DM, DM);
    gate_kernel<<<ROWS / 8, 256>>>(x, Wg, betab);
    dpfp_kernel<<<ROWS, 256>>>(qraw, qphi);
    dpfp_kernel<<<ROWS, 256>>>(kraw, kphi);
    scan_kernel<<<(BATCH * NHEAD * DK) / 8, 256>>>(qphi, kphi, vbuf, betab, attb);
    gemm_tf32<<<gg, 256>>>(attb, Wo, bo, out, ROWS, DM, DM);
}

// round 2
// speedup vs baseline: 1.0623x; 1.0623x over previous
#include <cuda_runtime.h>
#include <cstdint>
#include <cstddef>

#define SEQ   4096
#define BATCH 8
#define DM    512
#define NHEAD 8
#define DK    64
#define PHI   128
#define ROWS  (SEQ * BATCH)    // 32768 tokens
#define NG    1664             // fused QKV+gate GEMM width: 512*3 + 128 (gate pad)

// ---------------------------------------------------------------------------
// Static device scratch (allocations forbidden). Scan-facing buffers padded by
// one extra time step (BATCH tokens) for branch-free prefetch.
// ---------------------------------------------------------------------------
__device__ float g_xr  [(size_t)ROWS * DM];                    // x rounded to tf32
__device__ float g_wcat[(size_t)DM * NG];                      // Wq|Wk|Wv|Wg(pad) rounded
__device__ float g_wo  [(size_t)DM * DM];                      // Wo rounded
__device__ float g_qkv [(size_t)(ROWS + BATCH) * NG];          // fused GEMM out
__device__ float g_qphi[(size_t)(ROWS + BATCH) * NHEAD * PHI];
__device__ float g_kphi[(size_t)(ROWS + BATCH) * NHEAD * PHI];
__device__ float g_beta[(size_t)(ROWS + BATCH) * NHEAD];
__device__ float g_ckq [(size_t)(ROWS + BATCH) * NHEAD];       // <k,q> per (t,h)
__device__ float g_att [(size_t)ROWS * DM];                    // scan out (tf32-rounded)

// ---------------------------------------------------------------------------
// helpers
// ---------------------------------------------------------------------------
__device__ __forceinline__ uint32_t f2tf32(float x) {
    uint32_t r;
    asm("cvt.rna.tf32.f32 %0, %1;" : "=r"(r) : "f"(x));
    return r;
}
__device__ __forceinline__ float rnd_tf32(float x) {
    return __uint_as_float(f2tf32(x));
}
__device__ __forceinline__ void mma_tf32(float c[4], const uint32_t a[4], const uint32_t b[2]) {
    asm volatile(
        "mma.sync.aligned.m16n8k8.row.col.f32.tf32.tf32.f32 "
        "{%0,%1,%2,%3}, {%4,%5,%6,%7}, {%8,%9}, {%0,%1,%2,%3};\n"
        : "+f"(c[0]), "+f"(c[1]), "+f"(c[2]), "+f"(c[3])
        : "r"(a[0]), "r"(a[1]), "r"(a[2]), "r"(a[3]), "r"(b[0]), "r"(b[1]));
}
__device__ __forceinline__ void cp_async16(uint32_t s, const void* g) {
    asm volatile("cp.async.cg.shared.global [%0], [%1], 16;\n" :: "r"(s), "l"(g));
}
__device__ __forceinline__ void cp_commit() {
    asm volatile("cp.async.commit_group;\n" ::: "memory");
}
__device__ __forceinline__ void cp_wait0() {
    asm volatile("cp.async.wait_group 0;\n" ::: "memory");
}

// ---------------------------------------------------------------------------
// Elementwise pre-round passes (inputs already tf32 => hot GEMM loop has no cvt)
// ---------------------------------------------------------------------------
__global__ void __launch_bounds__(256)
round_f4(const float* __restrict__ in, float* __restrict__ out) {
    size_t i = ((size_t)blockIdx.x * 256 + threadIdx.x) * 4;
    float4 v = *reinterpret_cast<const float4*>(in + i);
    v.x = rnd_tf32(v.x); v.y = rnd_tf32(v.y); v.z = rnd_tf32(v.z); v.w = rnd_tf32(v.w);
    *reinterpret_cast<float4*>(out + i) = v;
}

__global__ void __launch_bounds__(256)
concat_w(const float* __restrict__ Wq, const float* __restrict__ Wk,
         const float* __restrict__ Wv, const float* __restrict__ Wg,
         float* __restrict__ wc) {
    int idx = blockIdx.x * 256 + threadIdx.x;     // 0 .. 512*1664-1
    int r = idx / NG, c = idx - r * NG;
    float v = 0.f;
    if      (c < 512)  v = Wq[r * 512 + c];
    else if (c < 1024) v = Wk[r * 512 + c - 512];
    else if (c < 1536) v = Wv[r * 512 + c - 1024];
    else if (c < 1544) v = Wg[r * 8 + c - 1536];
    wc[idx] = rnd_tf32(v);
}

// ---------------------------------------------------------------------------
// GEMM: C[M,N] = A[M,K]*B[K,N] (+bias). Inputs pre-rounded to tf32.
// 128x128x32 tile, 2-stage cp.async pipeline, 256 threads, 2 CTAs/SM.
// ---------------------------------------------------------------------------
#define BM 128
#define BN 128
#define BK 32
#define AST 36     // A smem row stride (floats), conflict-free, 16B-aligned rows
#define BST 136    // B smem row stride
#define STAGE_F (BM * AST + BK * BST)   // 8960 floats per stage
#define GEMM_SMEM_BYTES (2 * STAGE_F * 4)

__global__ void __launch_bounds__(256, 2)
gemm_tf32(const float* __restrict__ A, const float* __restrict__ B,
          const float* __restrict__ bias, float* __restrict__ C,
          int M, int N, int K)
{
    extern __shared__ float smemf[];

    const int tid  = threadIdx.x;
    const int warp = tid >> 5;
    const int lane = tid & 31;
    const int wm   = warp >> 2;
    const int wn   = warp & 3;
    const int g    = lane >> 2;
    const int t4   = lane & 3;
    const int rowBase = blockIdx.y * BM;
    const int colBase = blockIdx.x * BN;

    // load addressing
    const int ar = tid >> 3, ac = (tid & 7) << 2;   // A: 4 rows/thread (ar+32i), float4
    const int br = tid >> 5, bc = (tid & 31) << 2;  // B: 4 rows/thread (br+8i), float4

    float acc[4][4][4];
    #pragma unroll
    for (int i = 0; i < 4; ++i)
        #pragma unroll
        for (int j = 0; j < 4; ++j)
            #pragma unroll
            for (int r = 0; r < 4; ++r) acc[i][j][r] = 0.f;

    auto load_tile = [&](int stage, int k0) {
        float* as = smemf + stage * STAGE_F;
        float* bs = as + BM * AST;
        const float* ag = A + (size_t)(rowBase + ar) * K + k0 + ac;
        uint32_t asa = (uint32_t)__cvta_generic_to_shared(as + ar * AST + ac);
        #pragma unroll
        for (int i = 0; i < 4; ++i)
            cp_async16(asa + i * 32 * AST * 4, ag + (size_t)i * 32 * K);
        const float* bg = B + (size_t)(k0 + br) * N + colBase + bc;
        uint32_t bsa = (uint32_t)__cvta_generic_to_shared(bs + br * BST + bc);
        #pragma unroll
        for (int i = 0; i < 4; ++i)
            cp_async16(bsa + i * 8 * BST * 4, bg + (size_t)i * 8 * N);
        cp_commit();
    };

    const int NK = K / BK;
    load_tile(0, 0);

    for (int it = 0; it < NK; ++it) {
        cp_wait0();
        __syncthreads();
        if (it + 1 < NK) load_tile((it + 1) & 1, (it + 1) * BK);

        const uint32_t* as = reinterpret_cast<const uint32_t*>(smemf + (it & 1) * STAGE_F);
        const uint32_t* bs = as + BM * AST;

        #pragma unroll
        for (int kk = 0; kk < BK; kk += 8) {
            uint32_t afr[4][4];
            uint32_t bfr[4][2];
            #pragma unroll
            for (int mt = 0; mt < 4; ++mt) {
                int r0 = wm * 64 + mt * 16;
                afr[mt][0] = as[(r0 + g)     * AST + kk + t4];
                afr[mt][1] = as[(r0 + 8 + g) * AST + kk + t4];
                afr[mt][2] = as[(r0 + g)     * AST + kk + 4 + t4];
                afr[mt][3] = as[(r0 + 8 + g) * AST + kk + 4 + t4];
            }
            #pragma unroll
            for (int nt = 0; nt < 4; ++nt) {
                int c0 = wn * 32 + nt * 8;
                bfr[nt][0] = bs[(kk + t4)     * BST + c0 + g];
                bfr[nt][1] = bs[(kk + 4 + t4) * BST + c0 + g];
            }
            #pragma unroll
            for (int mt = 0; mt < 4; ++mt)
                #pragma unroll
                for (int nt = 0; nt < 4; ++nt)
                    mma_tf32(acc[mt][nt], afr[mt], bfr[nt]);
        }
    }

    #pragma unroll
    for (int mt = 0; mt < 4; ++mt) {
        int r = rowBase + wm * 64 + mt * 16 + g;
        #pragma unroll
        for (int nt = 0; nt < 4; ++nt) {
            int c = colBase + wn * 32 + nt * 8 + 2 * t4;
            float b0 = 0.f, b1 = 0.f;
            if (bias) { b0 = bias[c]; b1 = bias[c + 1]; }
            C[(size_t)r * N + c]           = acc[mt][nt][0] + b0;
            C[(size_t)r * N + c + 1]       = acc[mt][nt][1] + b1;
            C[(size_t)(r + 8) * N + c]     = acc[mt][nt][2] + b0;
            C[(size_t)(r + 8) * N + c + 1] = acc[mt][nt][3] + b1;
        }
    }
}

// ---------------------------------------------------------------------------
// beta[t,h] = sigmoid(qkv[t, 1536+h])
// ---------------------------------------------------------------------------
__global__ void __launch_bounds__(256)
extract_beta(const float* __restrict__ qkv, float* __restrict__ beta) {
    int idx = blockIdx.x * 256 + threadIdx.x;   // 0 .. ROWS*8-1
    int t = idx >> 3, h = idx & 7;
    float a = qkv[(size_t)t * NG + 1536 + h];
    beta[idx] = 1.f / (1.f + expf(-a));
}

// ---------------------------------------------------------------------------
// DPFP. One warp per (token, head). raw comes from the fused qkv buffer.
// When otherPhi != null (q pass), also emits ckq[t,h] = <phi_q, phi_k>.
// ---------------------------------------------------------------------------
__global__ void __launch_bounds__(256)
dpfp_kernel(const float* __restrict__ raw, float* __restrict__ phi,
            const float* __restrict__ otherPhi, float* __restrict__ ckq)
{
    const int t    = blockIdx.x;
    const int h    = threadIdx.x >> 5;
    const int lane = threadIdx.x & 31;

    const float4 xv = *reinterpret_cast<const float4*>(
        raw + (size_t)t * NG + h * DK + ((lane & 15) << 2));
    const float sgn = (lane < 16) ? 1.f : -1.f;
    float a0 = fmaxf(sgn * xv.x, 0.f);
    float a1 = fmaxf(sgn * xv.y, 0.f);
    float a2 = fmaxf(sgn * xv.z, 0.f);
    float a3 = fmaxf(sgn * xv.w, 0.f);

    float nbr = __shfl_sync(0xffffffffu, a3, (lane + 31) & 31);
    float y0 = a0 * nbr;
    float y1 = a1 * a0;
    float y2 = a2 * a1;
    float y3 = a3 * a2;

    float s = (y0 + y1) + (y2 + y3);
    float c = 0.f;
    if (otherPhi) {
        const float4 kv = *reinterpret_cast<const float4*>(
            otherPhi + ((size_t)t * NHEAD + h) * PHI + (lane << 2));
        c = fmaf(y0, kv.x, fmaf(y1, kv.y, fmaf(y2, kv.z, y3 * kv.w)));
    }
    #pragma unroll
    for (int off = 16; off > 0; off >>= 1) {
        s += __shfl_xor_sync(0xffffffffu, s, off);
        c += __shfl_xor_sync(0xffffffffu, c, off);
    }
    float r = 1.f / (s + 1e-6f);

    float4 o = make_float4(y0 * r, y1 * r, y2 * r, y3 * r);
    *reinterpret_cast<float4*>(phi + ((size_t)t * NHEAD + h) * PHI + (lane << 2)) = o;
    if (otherPhi && lane == 0)
        ckq[(size_t)t * NHEAD + h] = c * r;
}

// ---------------------------------------------------------------------------
// Delta-rule scan, one warp per (b,h,row). Carried chain shortened using
//   out = <W_old, q> + d * <k, q>   (ckq precomputed)
// so the two allreduces are independent and interleave.
// Output is stored pre-rounded to tf32 for the final GEMM.
// ---------------------------------------------------------------------------
__global__ void __launch_bounds__(256)
scan_kernel(const float* __restrict__ qphi, const float* __restrict__ kphi,
            const float* __restrict__ qkv, const float* __restrict__ beta,
            const float* __restrict__ ckq, float* __restrict__ att)
{
    const int w    = blockIdx.x * 8 + (threadIdx.x >> 5);  // 0..4095
    const int lane = threadIdx.x & 31;
    const int pair = w >> 6;
    const int row  = w & 63;
    const int b    = pair >> 3;
    const int h    = pair & 7;

    const int KQ_STRIDE = BATCH * NHEAD * PHI;  // 8192
    const int V_STRIDE  = BATCH * NG;           // 13312
    const int O_STRIDE  = BATCH * DM;           // 4096
    const int B_STRIDE  = BATCH * NHEAD;        // 64

    const float* kp = kphi + ((size_t)(b * NHEAD + h)) * PHI + (lane << 2);
    const float* qp = qphi + ((size_t)(b * NHEAD + h)) * PHI + (lane << 2);
    const float* vp = qkv  + (size_t)b * NG + 1024 + h * DK + row;
    const float* bp = beta + (size_t)b * NHEAD + h;
    const float* cp = ckq  + (size_t)b * NHEAD + h;
    uint32_t*    op = reinterpret_cast<uint32_t*>(att + (size_t)b * DM + h * DK + row);

    float w0 = 0.f, w1 = 0.f, w2 = 0.f, w3 = 0.f;

    float4 kk = *reinterpret_cast<const float4*>(kp);
    float4 qq = *reinterpret_cast<const float4*>(qp);
    float  vv = *vp;
    float  be = *bp;
    float  ck = *cp;

    for (int s = 0; s < SEQ; ++s) {
        kp += KQ_STRIDE; qp += KQ_STRIDE; vp += V_STRIDE; bp += B_STRIDE; cp += B_STRIDE;
        const float4 kn = *reinterpret_cast<const float4*>(kp);
        const float4 qn = *reinterpret_cast<const float4*>(qp);
        const float  vn = *vp;
        const float  bn = *bp;
        const float  cn = *cp;

        float s1 = fmaf(w0, kk.x, fmaf(w1, kk.y, fmaf(w2, kk.z, w3 * kk.w)));
        float o0 = fmaf(w0, qq.x, fmaf(w1, qq.y, fmaf(w2, qq.z, w3 * qq.w)));
        #pragma unroll
        for (int off = 16; off > 0; off >>= 1) {
            s1 += __shfl_xor_sync(0xffffffffu, s1, off);
            o0 += __shfl_xor_sync(0xffffffffu, o0, off);
        }

        float d = be * (vv - s1);
        w0 = fmaf(d, kk.x, w0);
        w1 = fmaf(d, kk.y, w1);
        w2 = fmaf(d, kk.z, w2);
        w3 = fmaf(d, kk.w, w3);

        float out = fmaf(d, ck, o0);
        if (lane == 0) *op = f2tf32(out);
        op += O_STRIDE;

        kk = kn; qq = qn; vv = vn; be = bn; ck = cn;
    }
}

// ---------------------------------------------------------------------------
// Host launcher
// ---------------------------------------------------------------------------
extern "C" void kernel_launch(void* const* d_in, const int* in_sizes, int n_in,
                              void* d_out, int out_size)
{
    const float* x  = (const float*)d_in[0];
    const float* Wq = (const float*)d_in[1];
    const float* Wk = (const float*)d_in[2];
    const float* Wv = (const float*)d_in[3];
    const float* Wg = (const float*)d_in[4];
    const float* Wo = (const float*)d_in[5];
    const float* bo = (const float*)d_in[6];
    float* out = (float*)d_out;

    float *xr, *wcat, *wo, *qkv, *qphi, *kphi, *betab, *ckq, *attb;
    cudaGetSymbolAddress((void**)&xr,    g_xr);
    cudaGetSymbolAddress((void**)&wcat,  g_wcat);
    cudaGetSymbolAddress((void**)&wo,    g_wo);
    cudaGetSymbolAddress((void**)&qkv,   g_qkv);
    cudaGetSymbolAddress((void**)&qphi,  g_qphi);
    cudaGetSymbolAddress((void**)&kphi,  g_kphi);
    cudaGetSymbolAddress((void**)&betab, g_beta);
    cudaGetSymbolAddress((void**)&ckq,   g_ckq);
    cudaGetSymbolAddress((void**)&attb,  g_att);

    cudaFuncSetAttribute(gemm_tf32, cudaFuncAttributeMaxDynamicSharedMemorySize,
                         GEMM_SMEM_BYTES);

    // pre-round inputs to tf32
    round_f4<<<(ROWS * DM) / 1024, 256>>>(x, xr);
    concat_w<<<(DM * NG) / 256, 256>>>(Wq, Wk, Wv, Wg, wcat);
    round_f4<<<(DM * DM) / 1024, 256>>>(Wo, wo);

    // fused QKV + gate GEMM: [32768,512] x [512,1664]
    dim3 g1(NG / BN, ROWS / BM);
    gemm_tf32<<<g1, 256, GEMM_SMEM_BYTES>>>(xr, wcat, nullptr, qkv, ROWS, NG, DM);

    extract_beta<<<(ROWS * NHEAD) / 256, 256>>>(qkv, betab);
    dpfp_kernel<<<ROWS, 256>>>(qkv + 512, kphi, nullptr, nullptr);
    dpfp_kernel<<<ROWS, 256>>>(qkv,       qphi, kphi,    ckq);

    scan_kernel<<<(BATCH * NHEAD * DK) / 8, 256>>>(qphi, kphi, qkv, betab, ckq, attb);

    dim3 g2(DM / BN, ROWS / BM);
    gemm_tf32<<<g2, 256, GEMM_SMEM_BYTES>>>(attb, wo, bo, out, ROWS, DM, DM);
}

// round 5
// speedup vs baseline: 1.5245x; 1.4350x over previous
#include <cuda_runtime.h>
#include <cstdint>
#include <cstddef>

#define SEQ   4096
#define BATCH 8
#define DM    512
#define NHEAD 8
#define DK    64
#define PHI   128
#define ROWS  (SEQ * BATCH)    // 32768 tokens
#define NG    1664             // fused QKV+gate GEMM width: 512*3 + 128 (gate pad)
#define PD    4                // scan prefetch depth (steps)

// ---------------------------------------------------------------------------
// Static device scratch (allocations forbidden). Scan-facing buffers padded by
// PD extra time steps (PD*BATCH tokens) for branch-free deep prefetch.
// ---------------------------------------------------------------------------
__device__ float g_xr  [(size_t)ROWS * DM];                         // x rounded to tf32
__device__ float g_wcat[(size_t)DM * NG];                           // Wq|Wk|Wv|Wg(pad)
__device__ float g_wo  [(size_t)DM * DM];                           // Wo rounded
__device__ float g_qkv [(size_t)(ROWS + PD * BATCH) * NG];          // fused GEMM out
__device__ float g_qphi[(size_t)(ROWS + PD * BATCH) * NHEAD * PHI];
__device__ float g_kphi[(size_t)(ROWS + PD * BATCH) * NHEAD * PHI];
__device__ float g_bc  [(size_t)(ROWS + PD * BATCH) * NHEAD * 2];   // (beta, <k,q>)
__device__ float g_att [(size_t)ROWS * DM];                         // scan out

// ---------------------------------------------------------------------------
// helpers
// ---------------------------------------------------------------------------
__device__ __forceinline__ uint32_t f2tf32(float x) {
    uint32_t r;
    asm("cvt.rna.tf32.f32 %0, %1;" : "=r"(r) : "f"(x));
    return r;
}
__device__ __forceinline__ float rnd_tf32(float x) {
    return __uint_as_float(f2tf32(x));
}
__device__ __forceinline__ void mma_tf32(float c[4], const uint32_t a[4], const uint32_t b[2]) {
    asm volatile(
        "mma.sync.aligned.m16n8k8.row.col.f32.tf32.tf32.f32 "
        "{%0,%1,%2,%3}, {%4,%5,%6,%7}, {%8,%9}, {%0,%1,%2,%3};\n"
        : "+f"(c[0]), "+f"(c[1]), "+f"(c[2]), "+f"(c[3])
        : "r"(a[0]), "r"(a[1]), "r"(a[2]), "r"(a[3]), "r"(b[0]), "r"(b[1]));
}
__device__ __forceinline__ void cp_async16(uint32_t s, const void* g) {
    asm volatile("cp.async.cg.shared.global [%0], [%1], 16;\n" :: "r"(s), "l"(g));
}
__device__ __forceinline__ void cp_commit() {
    asm volatile("cp.async.commit_group;\n" ::: "memory");
}
__device__ __forceinline__ void cp_wait0() {
    asm volatile("cp.async.wait_group 0;\n" ::: "memory");
}

// ---------------------------------------------------------------------------
// Elementwise pre-round passes
// ---------------------------------------------------------------------------
__global__ void __launch_bounds__(256)
round_f4(const float* __restrict__ in, float* __restrict__ out) {
    size_t i = ((size_t)blockIdx.x * 256 + threadIdx.x) * 4;
    float4 v = *reinterpret_cast<const float4*>(in + i);
    v.x = rnd_tf32(v.x); v.y = rnd_tf32(v.y); v.z = rnd_tf32(v.z); v.w = rnd_tf32(v.w);
    *reinterpret_cast<float4*>(out + i) = v;
}

__global__ void __launch_bounds__(256)
concat_w(const float* __restrict__ Wq, const float* __restrict__ Wk,
         const float* __restrict__ Wv, const float* __restrict__ Wg,
         float* __restrict__ wc) {
    int idx = blockIdx.x * 256 + threadIdx.x;     // 0 .. 512*1664-1
    int r = idx / NG, c = idx - r * NG;
    float v = 0.f;
    if      (c < 512)  v = Wq[r * 512 + c];
    else if (c < 1024) v = Wk[r * 512 + c - 512];
    else if (c < 1536) v = Wv[r * 512 + c - 1024];
    else if (c < 1544) v = Wg[r * 8 + c - 1536];
    wc[idx] = rnd_tf32(v);
}

// ---------------------------------------------------------------------------
// GEMM: C[M,N] = A[M,K]*B[K,N] (+bias). Inputs pre-rounded to tf32.
// 128x128x32 tile, 2-stage cp.async pipeline, 256 threads, 2 CTAs/SM.
// ---------------------------------------------------------------------------
#define BM 128
#define BN 128
#define BK 32
#define AST 36
#define BST 136
#define STAGE_F (BM * AST + BK * BST)
#define GEMM_SMEM_BYTES (2 * STAGE_F * 4)

__global__ void __launch_bounds__(256, 2)
gemm_tf32(const float* __restrict__ A, const float* __restrict__ B,
          const float* __restrict__ bias, float* __restrict__ C,
          int M, int N, int K)
{
    extern __shared__ float smemf[];

    const int tid  = threadIdx.x;
    const int warp = tid >> 5;
    const int lane = tid & 31;
    const int wm   = warp >> 2;
    const int wn   = warp & 3;
    const int g    = lane >> 2;
    const int t4   = lane & 3;
    const int rowBase = blockIdx.y * BM;
    const int colBase = blockIdx.x * BN;

    const int ar = tid >> 3, ac = (tid & 7) << 2;
    const int br = tid >> 5, bc = (tid & 31) << 2;

    float acc[4][4][4];
    #pragma unroll
    for (int i = 0; i < 4; ++i)
        #pragma unroll
        for (int j = 0; j < 4; ++j)
            #pragma unroll
            for (int r = 0; r < 4; ++r) acc[i][j][r] = 0.f;

    auto load_tile = [&](int stage, int k0) {
        float* as = smemf + stage * STAGE_F;
        float* bs = as + BM * AST;
        const float* ag = A + (size_t)(rowBase + ar) * K + k0 + ac;
        uint32_t asa = (uint32_t)__cvta_generic_to_shared(as + ar * AST + ac);
        #pragma unroll
        for (int i = 0; i < 4; ++i)
            cp_async16(asa + i * 32 * AST * 4, ag + (size_t)i * 32 * K);
        const float* bg = B + (size_t)(k0 + br) * N + colBase + bc;
        uint32_t bsa = (uint32_t)__cvta_generic_to_shared(bs + br * BST + bc);
        #pragma unroll
        for (int i = 0; i < 4; ++i)
            cp_async16(bsa + i * 8 * BST * 4, bg + (size_t)i * 8 * N);
        cp_commit();
    };

    const int NK = K / BK;
    load_tile(0, 0);

    for (int it = 0; it < NK; ++it) {
        cp_wait0();
        __syncthreads();
        if (it + 1 < NK) load_tile((it + 1) & 1, (it + 1) * BK);

        const uint32_t* as = reinterpret_cast<const uint32_t*>(smemf + (it & 1) * STAGE_F);
        const uint32_t* bs = as + BM * AST;

        #pragma unroll
        for (int kk = 0; kk < BK; kk += 8) {
            uint32_t afr[4][4];
            uint32_t bfr[4][2];
            #pragma unroll
            for (int mt = 0; mt < 4; ++mt) {
                int r0 = wm * 64 + mt * 16;
                afr[mt][0] = as[(r0 + g)     * AST + kk + t4];
                afr[mt][1] = as[(r0 + 8 + g) * AST + kk + t4];
                afr[mt][2] = as[(r0 + g)     * AST + kk + 4 + t4];
                afr[mt][3] = as[(r0 + 8 + g) * AST + kk + 4 + t4];
            }
            #pragma unroll
            for (int nt = 0; nt < 4; ++nt) {
                int c0 = wn * 32 + nt * 8;
                bfr[nt][0] = bs[(kk + t4)     * BST + c0 + g];
                bfr[nt][1] = bs[(kk + 4 + t4) * BST + c0 + g];
            }
            #pragma unroll
            for (int mt = 0; mt < 4; ++mt)
                #pragma unroll
                for (int nt = 0; nt < 4; ++nt)
                    mma_tf32(acc[mt][nt], afr[mt], bfr[nt]);
        }
    }

    #pragma unroll
    for (int mt = 0; mt < 4; ++mt) {
        int r = rowBase + wm * 64 + mt * 16 + g;
        #pragma unroll
        for (int nt = 0; nt < 4; ++nt) {
            int c = colBase + wn * 32 + nt * 8 + 2 * t4;
            float b0 = 0.f, b1 = 0.f;
            if (bias) { b0 = bias[c]; b1 = bias[c + 1]; }
            C[(size_t)r * N + c]           = acc[mt][nt][0] + b0;
            C[(size_t)r * N + c + 1]       = acc[mt][nt][1] + b1;
            C[(size_t)(r + 8) * N + c]     = acc[mt][nt][2] + b0;
            C[(size_t)(r + 8) * N + c + 1] = acc[mt][nt][3] + b1;
        }
    }
}

// ---------------------------------------------------------------------------
// bc[t,h].x = sigmoid(qkv[t,1536+h])   (.y = <k,q> filled by dpfp q-pass)
// ---------------------------------------------------------------------------
__global__ void __launch_bounds__(256)
extract_beta(const float* __restrict__ qkv, float* __restrict__ bcv) {
    int idx = blockIdx.x * 256 + threadIdx.x;   // 0 .. ROWS*8-1
    int t = idx >> 3, h = idx & 7;
    float a = qkv[(size_t)t * NG + 1536 + h];
    bcv[idx * 2] = 1.f / (1.f + expf(-a));
}

// ---------------------------------------------------------------------------
// DPFP. One warp per (token, head). When otherPhi != null (q pass), also
// emits bc[t,h].y = <phi_q, phi_k>.
// ---------------------------------------------------------------------------
__global__ void __launch_bounds__(256)
dpfp_kernel(const float* __restrict__ raw, float* __restrict__ phi,
            const float* __restrict__ otherPhi, float* __restrict__ bcv)
{
    const int t    = blockIdx.x;
    const int h    = threadIdx.x >> 5;
    const int lane = threadIdx.x & 31;

    const float4 xv = *reinterpret_cast<const float4*>(
        raw + (size_t)t * NG + h * DK + ((lane & 15) << 2));
    const float sgn = (lane < 16) ? 1.f : -1.f;
    float a0 = fmaxf(sgn * xv.x, 0.f);
    float a1 = fmaxf(sgn * xv.y, 0.f);
    float a2 = fmaxf(sgn * xv.z, 0.f);
    float a3 = fmaxf(sgn * xv.w, 0.f);

    float nbr = __shfl_sync(0xffffffffu, a3, (lane + 31) & 31);
    float y0 = a0 * nbr;
    float y1 = a1 * a0;
    float y2 = a2 * a1;
    float y3 = a3 * a2;

    float s = (y0 + y1) + (y2 + y3);
    float c = 0.f;
    if (otherPhi) {
        const float4 kv = *reinterpret_cast<const float4*>(
            otherPhi + ((size_t)t * NHEAD + h) * PHI + (lane << 2));
        c = fmaf(y0, kv.x, fmaf(y1, kv.y, fmaf(y2, kv.z, y3 * kv.w)));
    }
    #pragma unroll
    for (int off = 16; off > 0; off >>= 1) {
        s += __shfl_xor_sync(0xffffffffu, s, off);
        c += __shfl_xor_sync(0xffffffffu, c, off);
    }
    float r = 1.f / (s + 1e-6f);

    float4 o = make_float4(y0 * r, y1 * r, y2 * r, y3 * r);
    *reinterpret_cast<float4*>(phi + ((size_t)t * NHEAD + h) * PHI + (lane << 2)) = o;
    if (otherPhi && lane == 0)
        bcv[((size_t)t * NHEAD + h) * 2 + 1] = c * r;
}

// ---------------------------------------------------------------------------
// Delta-rule scan, one warp per (b,h,row). Carried chain shortened using
//   out = <W_old, q> + d * <k, q>   (ckq precomputed)
// Register ring buffers prefetch PD=4 steps ahead (MLP>=4 hides DRAM/L2
// latency). Interleaved butterfly allreduces for s1/o0.
// ---------------------------------------------------------------------------
__global__ void __launch_bounds__(256)
scan_kernel(const float* __restrict__ qphi, const float* __restrict__ kphi,
            const float* __restrict__ qkv, const float* __restrict__ bcv,
            float* __restrict__ att)
{
    const int w    = blockIdx.x * 8 + (threadIdx.x >> 5);  // 0..4095
    const int lane = threadIdx.x & 31;
    const int pair = w >> 6;
    const int row  = w & 63;
    const int b    = pair >> 3;
    const int h    = pair & 7;

    const int KQ_STRIDE = BATCH * NHEAD * PHI;     // 8192
    const int V_STRIDE  = BATCH * NG;              // 13312
    const int O_STRIDE  = BATCH * DM;              // 4096
    const int BC_STRIDE = BATCH * NHEAD;           // 64 float2

    const float*  kp = kphi + ((size_t)(b * NHEAD + h)) * PHI + (lane << 2);
    const float*  qp = qphi + ((size_t)(b * NHEAD + h)) * PHI + (lane << 2);
    const float*  vp = qkv  + (size_t)b * NG + 1024 + h * DK + row;
    const float2* bp = reinterpret_cast<const float2*>(bcv) + (size_t)b * NHEAD + h;
    uint32_t*     op = reinterpret_cast<uint32_t*>(att + (size_t)b * DM + h * DK + row);

    float w0 = 0.f, w1 = 0.f, w2 = 0.f, w3 = 0.f;

    // deep prefetch ring (statically indexed via full unroll)
    float4 kb[PD], qb[PD];
    float  vb[PD];
    float2 bb[PD];
    #pragma unroll
    for (int i = 0; i < PD; ++i) {
        kb[i] = *reinterpret_cast<const float4*>(kp);
        qb[i] = *reinterpret_cast<const float4*>(qp);
        vb[i] = *vp;
        bb[i] = *bp;
        kp += KQ_STRIDE; qp += KQ_STRIDE; vp += V_STRIDE; bp += BC_STRIDE;
    }

    for (int s = 0; s < SEQ; s += PD) {
        #pragma unroll
        for (int j = 0; j < PD; ++j) {
            const float4 kk = kb[j];
            const float4 qq = qb[j];
            const float  vv = vb[j];
            const float2 bc = bb[j];

            // prefetch step s+j+PD
            kb[j] = *reinterpret_cast<const float4*>(kp);
            qb[j] = *reinterpret_cast<const float4*>(qp);
            vb[j] = *vp;
            bb[j] = *bp;
            kp += KQ_STRIDE; qp += KQ_STRIDE; vp += V_STRIDE; bp += BC_STRIDE;

            float s1 = fmaf(w0, kk.x, fmaf(w1, kk.y, fmaf(w2, kk.z, w3 * kk.w)));
            float o0 = fmaf(w0, qq.x, fmaf(w1, qq.y, fmaf(w2, qq.z, w3 * qq.w)));
            #pragma unroll
            for (int off = 16; off > 0; off >>= 1) {
                s1 += __shfl_xor_sync(0xffffffffu, s1, off);
                o0 += __shfl_xor_sync(0xffffffffu, o0, off);
            }

            float d = bc.x * (vv - s1);
            w0 = fmaf(d, kk.x, w0);
            w1 = fmaf(d, kk.y, w1);
            w2 = fmaf(d, kk.z, w2);
            w3 = fmaf(d, kk.w, w3);

            float out = fmaf(d, bc.y, o0);
            if (lane == 0) *op = f2tf32(out);
            op += O_STRIDE;
        }
    }
}

// ---------------------------------------------------------------------------
// Host launcher
// ---------------------------------------------------------------------------
extern "C" void kernel_launch(void* const* d_in, const int* in_sizes, int n_in,
                              void* d_out, int out_size)
{
    const float* x  = (const float*)d_in[0];
    const float* Wq = (const float*)d_in[1];
    const float* Wk = (const float*)d_in[2];
    const float* Wv = (const float*)d_in[3];
    const float* Wg = (const float*)d_in[4];
    const float* Wo = (const float*)d_in[5];
    const float* bo = (const float*)d_in[6];
    float* out = (float*)d_out;

    float *xr, *wcat, *wo, *qkv, *qphi, *kphi, *bcv, *attb;
    cudaGetSymbolAddress((void**)&xr,    g_xr);
    cudaGetSymbolAddress((void**)&wcat,  g_wcat);
    cudaGetSymbolAddress((void**)&wo,    g_wo);
    cudaGetSymbolAddress((void**)&qkv,   g_qkv);
    cudaGetSymbolAddress((void**)&qphi,  g_qphi);
    cudaGetSymbolAddress((void**)&kphi,  g_kphi);
    cudaGetSymbolAddress((void**)&bcv,   g_bc);
    cudaGetSymbolAddress((void**)&attb,  g_att);

    cudaFuncSetAttribute(gemm_tf32, cudaFuncAttributeMaxDynamicSharedMemorySize,
                         GEMM_SMEM_BYTES);

    // pre-round inputs to tf32
    round_f4<<<(ROWS * DM) / 1024, 256>>>(x, xr);
    concat_w<<<(DM * NG) / 256, 256>>>(Wq, Wk, Wv, Wg, wcat);
    round_f4<<<(DM * DM) / 1024, 256>>>(Wo, wo);

    // fused QKV + gate GEMM: [32768,512] x [512,1664]
    dim3 g1(NG / BN, ROWS / BM);
    gemm_tf32<<<g1, 256, GEMM_SMEM_BYTES>>>(xr, wcat, nullptr, qkv, ROWS, NG, DM);

    extract_beta<<<(ROWS * NHEAD) / 256, 256>>>(qkv, bcv);
    dpfp_kernel<<<ROWS, 256>>>(qkv + 512, kphi, nullptr, nullptr);
    dpfp_kernel<<<ROWS, 256>>>(qkv,       qphi, kphi,    bcv);

    scan_kernel<<<(BATCH * NHEAD * DK) / 8, 256>>>(qphi, kphi, qkv, bcv, attb);

    dim3 g2(DM / BN, ROWS / BM);
    gemm_tf32<<<g2, 256, GEMM_SMEM_BYTES>>>(attb, wo, bo, out, ROWS, DM, DM);
}